// round 14
// baseline (speedup 1.0000x reference)
#include <cuda_runtime.h>
#include <cstdint>

#define B 64
#define K 8
#define V 128000
#define NV4    32000                 // float4 per row
#define SPLIT  5                     // CTAs per row in kA
#define NWARP  8                     // warps per CTA in kA
#define NT     (NWARP * 32)
#define BATCH  5                     // batches per warp (each batch = 1 chunk)
#define CH4    160                   // float4 per chunk (one batch: 5 iters x 32 lanes)
#define NCH    200                   // chunks per row = SPLIT*NWARP*BATCH
#define L2N    5                     // float4 per lane in kB level 2

// cross-kernel scratch (no allocations allowed)
__device__ int   g_j[B];
__device__ float g_u[B];
__device__ int   g_num[B];
__device__ int   g_all[B];
__device__ float g_csum[B * NCH];

// ---------------------------------------------------------------------------
// Kernel A: per-CTA accept-chain prologue + lean fp32 streaming pass.
// Same loads/batching as R12 (proven ~L2-speed); now each 160-float4 batch's
// sum is stored separately -> 200 fine chunks per row for cheap refinement.
// ---------------------------------------------------------------------------
__global__ void __launch_bounds__(NT)
kA_stream(const int* __restrict__ draft_ids,
          const float* __restrict__ draft_probs,
          const float* __restrict__ target_probs,
          const int* __restrict__ bonus,
          const float* __restrict__ uniforms,
          float* __restrict__ out, int out_size) {
    int bb = blockIdx.x;
    int b = bb / SPLIT, s = bb % SPLIT;
    int tid = threadIdx.x, w = tid >> 5, lane = tid & 31;

    __shared__ int sh_j, sh_all;

    if (w == 0) {
        int k = lane;
        bool  acc = false;
        float uu  = 0.0f;
        int   id  = 0;
        if (k < K) {
            id = draft_ids[b * K + k];
            uu = uniforms[b * K + k];
            size_t base = (size_t)(b * K + k) * (size_t)V + (size_t)id;
            float p = target_probs[base];
            float q = draft_probs[base];
            float ap = fminf(1.0f, __fdiv_rn(p, fmaxf(q, 1e-10f)));  // bit-exact vs ref
            acc = uu < ap;
        }
        unsigned m = __ballot_sync(0xffffffffu, acc) & 0xFFu;
        int num = __ffs(~m) - 1;
        int j   = (num < K - 1) ? num : (K - 1);
        int all = (num == K) ? 1 : 0;
        float uj = __shfl_sync(0xffffffffu, uu, j);

        if (lane == 0) { sh_j = j; sh_all = all; }

        if (s == 0) {
            if (k < K) {
                out[b * (K + 1) + k] = (k < num) ? (float)id : -1.0f;
            } else if (k == K) {
                out[b * (K + 1) + K] = all ? (float)bonus[b] : -1.0f;
            }
            if (lane == 0) {
                g_j[b]   = j;
                g_u[b]   = uj;
                g_num[b] = num;
                g_all[b] = all;
                if (out_size >= B * (K + 1) + 4 * B) {
                    out[B * (K + 1) + 0 * B + b] = (float)num;
                    out[B * (K + 1) + 1 * B + b] = (float)num;
                    out[B * (K + 1) + 2 * B + b] = (float)(1 - all);
                    out[B * (K + 1) + 3 * B + b] = (float)all;
                }
            }
        }
    }
    __syncthreads();

    if (sh_all) return;
    int j = sh_j;

    const float4* tg = reinterpret_cast<const float4*>(
        target_probs + ((size_t)b * K + (size_t)j) * (size_t)V);
    const float4* dr = reinterpret_cast<const float4*>(
        draft_probs + ((size_t)b * K + (size_t)j) * (size_t)V);
    int cb = (s * NWARP + w) * 800;    // warp covers 800 contiguous float4

    // batch ii covers the contiguous float4 span [cb+ii*160, cb+ii*160+160)
#pragma unroll
    for (int ii = 0; ii < BATCH; ii++) {
        float4 ta[BATCH], da[BATCH];
#pragma unroll
        for (int jj = 0; jj < BATCH; jj++) {
            int idx = cb + (ii * BATCH + jj) * 32 + lane;
            ta[jj] = __ldg(&tg[idx]);
            da[jj] = __ldg(&dr[idx]);
        }
        float part = 0.0f;
#pragma unroll
        for (int jj = 0; jj < BATCH; jj++) {
            part += fmaxf(ta[jj].x - da[jj].x, 0.0f)
                  + fmaxf(ta[jj].y - da[jj].y, 0.0f)
                  + fmaxf(ta[jj].z - da[jj].z, 0.0f)
                  + fmaxf(ta[jj].w - da[jj].w, 0.0f);
        }
#pragma unroll
        for (int off = 16; off; off >>= 1)
            part += __shfl_down_sync(0xffffffffu, part, off);
        if (lane == 0)
            g_csum[b * NCH + (s * NWARP + w) * BATCH + ii] = part;
    }
}

// inclusive fp64 warp scan
__device__ __forceinline__ double wscan(double v, int lane) {
#pragma unroll
    for (int off = 1; off < 32; off <<= 1) {
        double o = __shfl_up_sync(0xffffffffu, v, off);
        if (lane >= off) v += o;
    }
    return v;
}

// ---------------------------------------------------------------------------
// Kernel B: one warp per row; every level is one parallel load round trip.
// L1: 200 chunk sums (25 lanes x 8, register prefix + warp scan).
// L2: crossing 160-float4 chunk, 5 float4-pairs per lane.
// L3: crossing 5-float4 segment, lanes 0..4 (L1-hot).
// ---------------------------------------------------------------------------
__global__ void __launch_bounds__(32)
kB_pick(const float* __restrict__ draft_probs,
        const float* __restrict__ target_probs,
        float* __restrict__ out) {
    int b = blockIdx.x;
    if (g_all[b]) return;

    int lane = threadIdx.x;
    int j = g_j[b];
    float u = g_u[b];
    const float4* tg = reinterpret_cast<const float4*>(
        target_probs + ((size_t)b * K + (size_t)j) * (size_t)V);
    const float4* dr = reinterpret_cast<const float4*>(
        draft_probs + ((size_t)b * K + (size_t)j) * (size_t)V);

    // ---- Level 1: 200 chunk sums, 25 lanes x 8 contiguous ----
    double p8[8];
    double lsum = 0.0;
    if (lane < 25) {
        double acc = 0.0;
#pragma unroll
        for (int k = 0; k < 8; k++) {
            acc += (double)g_csum[b * NCH + lane * 8 + k];
            p8[k] = acc;
        }
        lsum = acc;
    } else {
#pragma unroll
        for (int k = 0; k < 8; k++) p8[k] = 0.0;
    }
    double sc1 = wscan(lsum, lane);
    double total = __shfl_sync(0xffffffffu, sc1, 31);

    if (!(total > 0.0)) {
        // fallback: full-row argmax of target (measure-zero on softmax data)
        float mv = -1.0f; int mi = 0;
        for (int i = lane; i < NV4; i += 32) {
            float4 t4 = tg[i];
            int e = i * 4;
            if (t4.x > mv) { mv = t4.x; mi = e; }
            if (t4.y > mv) { mv = t4.y; mi = e + 1; }
            if (t4.z > mv) { mv = t4.z; mi = e + 2; }
            if (t4.w > mv) { mv = t4.w; mi = e + 3; }
        }
#pragma unroll
        for (int off = 16; off; off >>= 1) {
            float ov = __shfl_down_sync(0xffffffffu, mv, off);
            int   oi = __shfl_down_sync(0xffffffffu, mi, off);
            if (ov > mv || (ov == mv && oi < mi)) { mv = ov; mi = oi; }
        }
        if (lane == 0) out[b * (K + 1) + g_num[b]] = (float)mi;
        return;
    }
    double t = (double)u * total;

    unsigned m1 = __ballot_sync(0xffffffffu, (lane < 25) && (sc1 > t));
    int L = m1 ? (__ffs(m1) - 1) : 24;                 // clamp on fp edge
    int cidx = 0; double basec = 0.0;
    if (lane == L) {
        double run = sc1 - lsum;                       // exclusive prefix
        int kk = 7;                                    // clamp default
#pragma unroll
        for (int k = 0; k < 8; k++) {
            if (run + p8[k] > t) { kk = k; break; }
        }
        cidx  = L * 8 + kk;
        basec = run + (kk ? p8[kk - 1] : 0.0);
    }
    int    c    = __shfl_sync(0xffffffffu, cidx, L);
    double base = __shfl_sync(0xffffffffu, basec, L);

    // ---- Level 2: crossing chunk (160 float4), 5 float4-pairs per lane ----
    int lb = c * CH4 + lane * L2N;
    float4 ta[L2N], da[L2N];
#pragma unroll
    for (int k = 0; k < L2N; k++) {
        ta[k] = __ldg(&tg[lb + k]);
        da[k] = __ldg(&dr[lb + k]);
    }
    float ls = 0.0f;
#pragma unroll
    for (int k = 0; k < L2N; k++) {
        ls += fmaxf(ta[k].x - da[k].x, 0.0f) + fmaxf(ta[k].y - da[k].y, 0.0f)
            + fmaxf(ta[k].z - da[k].z, 0.0f) + fmaxf(ta[k].w - da[k].w, 0.0f);
    }
    double sc2 = wscan((double)ls, lane);
    unsigned mm = __ballot_sync(0xffffffffu, (base + sc2) > t);
    int fl = mm ? (__ffs(mm) - 1) : 31;                // clamp on fp edge
    double run0 = base + __shfl_sync(0xffffffffu, sc2 - (double)ls, fl);

    // ---- Level 3: crossing 5-float4 segment, lanes 0..4 (L1-hot) ----
    int sb = c * CH4 + fl * L2N;
    double r0 = 0.0, p1 = 0.0, p2 = 0.0, p3 = 0.0;
    if (lane < L2N) {
        float4 t4 = tg[sb + lane];
        float4 d4 = dr[sb + lane];
        r0 = (double)fmaxf(t4.x - d4.x, 0.0f);
        p1 = r0 + (double)fmaxf(t4.y - d4.y, 0.0f);
        p2 = p1 + (double)fmaxf(t4.z - d4.z, 0.0f);
        p3 = p2 + (double)fmaxf(t4.w - d4.w, 0.0f);
    }
    double es = wscan(p3, lane);
    unsigned me = __ballot_sync(0xffffffffu, (lane < L2N) && (run0 + es > t));
    int fe = me ? (__ffs(me) - 1) : (L2N - 1);         // clamp on fp edge

    if (lane == fe) {
        double run = run0 + (es - p3);                 // exclusive prefix
        int sub = 3;                                   // clamp default
        if      (run + r0 > t) sub = 0;
        else if (run + p1 > t) sub = 1;
        else if (run + p2 > t) sub = 2;
        out[b * (K + 1) + g_num[b]] = (float)((sb + lane) * 4 + sub);
    }
}

// ---------------------------------------------------------------------------
extern "C" void kernel_launch(void* const* d_in, const int* in_sizes, int n_in,
                              void* d_out, int out_size) {
    const int*   draft_ids    = (const int*)d_in[0];
    const float* draft_probs  = (const float*)d_in[1];
    const float* target_probs = (const float*)d_in[2];
    const int*   bonus        = (const int*)d_in[3];
    const float* uniforms     = (const float*)d_in[4];
    float* out = (float*)d_out;

    kA_stream<<<B * SPLIT, NT>>>(draft_ids, draft_probs, target_probs, bonus,
                                 uniforms, out, out_size);
    kB_pick<<<B, 32>>>(draft_probs, target_probs, out);
}